// round 1
// baseline (speedup 1.0000x reference)
#include <cuda_runtime.h>
#include <math.h>
#include <stdint.h>

// Problem constants (B=2, H=16, L=S=2048, D=128, fp32)
#define BHN 32          // B*H
#define LQ  2048
#define SK  2048
#define DD  128
#define BM  64          // query rows per CTA
#define BN  64          // kv rows per iteration
#define NTHREADS 128

// Scratch: suffix sums of V  (suffv[bh][i][d] = sum_{s>=i} v[bh][s][d])
__device__ float g_suffv[(size_t)BHN * SK * DD];     // 32 MB
__device__ float g_segsum[BHN * 8 * DD];             // per-segment column sums

static const int SEG = SK / 8;  // 256

// ---------------------------------------------------------------------------
// Pass 1: per-segment column sums of V
__global__ void segsum_kernel(const float* __restrict__ V) {
    int bh = blockIdx.x, seg = blockIdx.y, d = threadIdx.x;
    const float* vp = V + ((size_t)bh * SK + (size_t)seg * SEG) * DD + d;
    float acc = 0.f;
#pragma unroll 8
    for (int s = 0; s < SEG; ++s) acc += vp[(size_t)s * DD];
    g_segsum[(bh * 8 + seg) * DD + d] = acc;
}

// Pass 2: suffix sums within each segment, seeded by later segments' sums
__global__ void suffix_kernel(const float* __restrict__ V) {
    int bh = blockIdx.x, seg = blockIdx.y, d = threadIdx.x;
    float acc = 0.f;
    for (int s2 = seg + 1; s2 < 8; ++s2) acc += g_segsum[(bh * 8 + s2) * DD + d];
    const float* vp = V + (size_t)bh * SK * DD + d;
    float* op = g_suffv + (size_t)bh * SK * DD + d;
#pragma unroll 4
    for (int s = seg * SEG + SEG - 1; s >= seg * SEG; --s) {
        acc += vp[(size_t)s * DD];
        op[(size_t)s * DD] = acc;
    }
}

// ---------------------------------------------------------------------------
// Flash-attention main kernel (fp32, CUDA cores), faithful to:
//   scores = clip(qk*scale, -50, 50) for s<=l;  = -50 for s>l (masked)
//   softmax over ALL S entries; out = A @ V
// Masked tail (s >= ntiles*BN) handled analytically via V suffix sums.
__global__ void __launch_bounds__(NTHREADS)
attn_kernel(const float* __restrict__ Q, const float* __restrict__ K,
            const float* __restrict__ V, float* __restrict__ Out)
{
    extern __shared__ float sm[];
    float* Qs  = sm;                 // [64][132]  (pad 132 -> conflict-free)
    float* KVs = sm + BM * 132;      // [64][132]  (K tile, then V tile)
    float* Ps  = sm + 2 * BM * 132;  // [64][72]

    const int bh  = blockIdx.y;
    const int qt  = blockIdx.x;
    const int l0  = qt * BM;
    const int tid = threadIdx.x;
    const int cg  = tid & 7;    // col-group (score) / d-group (PV)
    const int rg  = tid >> 3;   // row-group 0..15

    const float scale = 0.08838834764831845f;  // 1/sqrt(128)

    const float* Qg = Q + ((size_t)bh * LQ + l0) * DD;
    const float* Kg = K + (size_t)bh * SK * DD;
    const float* Vg = V + (size_t)bh * SK * DD;

    // Load Q tile (pre-scaled by 1/sqrt(D))
    {
        const float4* src = (const float4*)Qg;
#pragma unroll
        for (int i = 0; i < 16; ++i) {
            int f = i * NTHREADS + tid;
            float4 v4 = src[f];
            v4.x *= scale; v4.y *= scale; v4.z *= scale; v4.w *= scale;
            ((float4*)Qs)[(f >> 5) * 33 + (f & 31)] = v4;
        }
    }

    float m[4], rho[4];
    float o[4][16];
#pragma unroll
    for (int i = 0; i < 4; ++i) {
        m[i] = -1e30f; rho[i] = 0.f;
#pragma unroll
        for (int j = 0; j < 16; ++j) o[i][j] = 0.f;
    }

    const int ntiles = qt + 1;   // kv tiles intersecting the causal region
    for (int t = 0; t < ntiles; ++t) {
        const int s0 = t * BN;
        __syncthreads();  // prior PV-gemm readers of KVs done
        // Load K tile
        {
            const float4* src = (const float4*)(Kg + (size_t)s0 * DD);
#pragma unroll
            for (int i = 0; i < 16; ++i) {
                int f = i * NTHREADS + tid;
                ((float4*)KVs)[(f >> 5) * 33 + (f & 31)] = src[f];
            }
        }
        __syncthreads();

        // Score GEMM: acc[4][8] = Qtile(4 rows: rg+16i) . Ktile(8 cols: cg+8j)
        float acc[4][8];
#pragma unroll
        for (int i = 0; i < 4; ++i)
#pragma unroll
            for (int j = 0; j < 8; ++j) acc[i][j] = 0.f;

#pragma unroll 8
        for (int k4 = 0; k4 < 32; ++k4) {
            float4 qf[4], kf[8];
#pragma unroll
            for (int i = 0; i < 4; ++i)
                qf[i] = ((const float4*)Qs)[(rg + 16 * i) * 33 + k4];
#pragma unroll
            for (int j = 0; j < 8; ++j)
                kf[j] = ((const float4*)KVs)[(cg + 8 * j) * 33 + k4];
#pragma unroll
            for (int i = 0; i < 4; ++i)
#pragma unroll
                for (int j = 0; j < 8; ++j) {
                    acc[i][j] += qf[i].x * kf[j].x;
                    acc[i][j] += qf[i].y * kf[j].y;
                    acc[i][j] += qf[i].z * kf[j].z;
                    acc[i][j] += qf[i].w * kf[j].w;
                }
        }

        // Clip + causal mask (-50 for masked, matching clip-after-mask), online softmax
#pragma unroll
        for (int i = 0; i < 4; ++i) {
            const int lgl = l0 + rg + 16 * i;
            float tmax = -1e30f;
#pragma unroll
            for (int j = 0; j < 8; ++j) {
                int sg = s0 + cg + 8 * j;
                float v = fminf(fmaxf(acc[i][j], -50.f), 50.f);
                if (sg > lgl) v = -50.f;
                acc[i][j] = v;
                tmax = fmaxf(tmax, v);
            }
            tmax = fmaxf(tmax, __shfl_xor_sync(0xffffffffu, tmax, 1));
            tmax = fmaxf(tmax, __shfl_xor_sync(0xffffffffu, tmax, 2));
            tmax = fmaxf(tmax, __shfl_xor_sync(0xffffffffu, tmax, 4));
            float mnew  = fmaxf(m[i], tmax);
            float alpha = __expf(m[i] - mnew);
            float psum = 0.f;
#pragma unroll
            for (int j = 0; j < 8; ++j) {
                float p = __expf(acc[i][j] - mnew);
                acc[i][j] = p;
                psum += p;
            }
            psum += __shfl_xor_sync(0xffffffffu, psum, 1);
            psum += __shfl_xor_sync(0xffffffffu, psum, 2);
            psum += __shfl_xor_sync(0xffffffffu, psum, 4);
            rho[i] = rho[i] * alpha + psum;
            m[i]   = mnew;
#pragma unroll
            for (int j = 0; j < 16; ++j) o[i][j] *= alpha;
#pragma unroll
            for (int j = 0; j < 8; ++j)
                Ps[(rg + 16 * i) * 72 + cg + 8 * j] = acc[i][j];
        }
        __syncthreads();   // Ps visible; score-gemm readers of KVs done

        // Load V tile into the same buffer
        {
            const float4* src = (const float4*)(Vg + (size_t)s0 * DD);
#pragma unroll
            for (int i = 0; i < 16; ++i) {
                int f = i * NTHREADS + tid;
                ((float4*)KVs)[(f >> 5) * 33 + (f & 31)] = src[f];
            }
        }
        __syncthreads();

        // PV GEMM: o[4 rows][16 d] += P[4 rows][64] * V[64][16 d]
#pragma unroll 4
        for (int s = 0; s < BN; ++s) {
            float pf[4];
#pragma unroll
            for (int i = 0; i < 4; ++i)
                pf[i] = Ps[(rg + 16 * i) * 72 + s];
            float4 vf[4];
#pragma unroll
            for (int j = 0; j < 4; ++j)
                vf[j] = ((const float4*)KVs)[s * 33 + cg + 8 * j];
#pragma unroll
            for (int i = 0; i < 4; ++i)
#pragma unroll
                for (int j = 0; j < 4; ++j) {
                    o[i][4 * j + 0] += pf[i] * vf[j].x;
                    o[i][4 * j + 1] += pf[i] * vf[j].y;
                    o[i][4 * j + 2] += pf[i] * vf[j].z;
                    o[i][4 * j + 3] += pf[i] * vf[j].w;
                }
        }
    }

    // Epilogue: add masked tail via V suffix sums, normalize, store.
    const int sbase = ntiles * BN;          // first kv index never visited
    const int nrem  = SK - sbase;           // # masked entries not in any tile
    const float4* sfp = (const float4*)(g_suffv + ((size_t)bh * SK + sbase) * DD);
#pragma unroll
    for (int i = 0; i < 4; ++i) {
        const int lgl = l0 + rg + 16 * i;
        float w   = __expf(-50.f - m[i]);
        float inv = 1.f / (rho[i] + (float)nrem * w);
        float4* outp = (float4*)(Out + ((size_t)bh * LQ + lgl) * DD);
#pragma unroll
        for (int j = 0; j < 4; ++j) {
            int c4 = cg + 8 * j;
            float4 sv = make_float4(0.f, 0.f, 0.f, 0.f);
            if (nrem > 0) sv = sfp[c4];
            float4 r;
            r.x = (o[i][4 * j + 0] + w * sv.x) * inv;
            r.y = (o[i][4 * j + 1] + w * sv.y) * inv;
            r.z = (o[i][4 * j + 2] + w * sv.z) * inv;
            r.w = (o[i][4 * j + 3] + w * sv.w) * inv;
            outp[c4] = r;
        }
    }
}

// ---------------------------------------------------------------------------
extern "C" void kernel_launch(void* const* d_in, const int* in_sizes, int n_in,
                              void* d_out, int out_size) {
    (void)in_sizes; (void)n_in; (void)out_size;
    const float* q = (const float*)d_in[0];
    const float* k = (const float*)d_in[1];
    const float* v = (const float*)d_in[2];
    float* out = (float*)d_out;

    // V suffix sums (masked-tail correction data)
    segsum_kernel<<<dim3(BHN, 8), DD>>>(v);
    suffix_kernel<<<dim3(BHN, 8), DD>>>(v);

    const int smem_bytes = (2 * BM * 132 + BM * 72) * (int)sizeof(float); // 86016
    cudaFuncSetAttribute(attn_kernel,
                         cudaFuncAttributeMaxDynamicSharedMemorySize, smem_bytes);
    attn_kernel<<<dim3(LQ / BM, BHN), NTHREADS, smem_bytes>>>(q, k, v, out);
}

// round 3
// speedup vs baseline: 3.8962x; 3.8962x over previous
#include <cuda_runtime.h>
#include <cstdint>

// B=2,H=16,L=S=2048,D=128 fp32, causal, clip(-50,50) applied AFTER mask.
#define BH   32
#define LL   2048
#define DD   128
#define BM   128
#define BN   64
#define NQT  16          // LL/BM
#define NTHR 256

// tf32(RN)-rounded copies of K and V
__device__ float g_kr[(size_t)BH * LL * DD];
__device__ float g_vr[(size_t)BH * LL * DD];

// SMEM layout (floats)
#define QS_OFF   0
#define QS_STR   132
#define KS_OFF   (QS_OFF + 128 * 132)          // 16896
#define KS_STR   132
#define VS_OFF   (KS_OFF + 64 * 132)           // 25344
#define VS_STR   136
#define VS_BUF   (64 * 136)                    // 8704 floats per buffer
#define PS_OFF   (VS_OFF + 2 * VS_BUF)         // 42752
#define PS_STR   68
#define RHO_OFF  (PS_OFF + 128 * 68)           // 51456
#define SMEM_FLOATS (RHO_OFF + 256)            // 51712
#define SMEM_BYTES  (SMEM_FLOATS * 4)          // 206848

__device__ __forceinline__ uint32_t smem_u32(const void* p) {
    uint32_t a;
    asm("{ .reg .u64 t; cvta.to.shared.u64 t, %1; cvt.u32.u64 %0, t; }" : "=r"(a) : "l"(p));
    return a;
}
#define CP_ASYNC16(dst, src) asm volatile("cp.async.cg.shared.global [%0], [%1], 16;" :: "r"(dst), "l"(src) : "memory")
#define CP_COMMIT()          asm volatile("cp.async.commit_group;" ::: "memory")
#define CP_WAIT0()           asm volatile("cp.async.wait_group 0;" ::: "memory")

__device__ __forceinline__ void mma_tf32(float c[4], const uint32_t a[4], const uint32_t b[2]) {
    asm volatile(
        "mma.sync.aligned.m16n8k8.row.col.f32.tf32.tf32.f32 "
        "{%0,%1,%2,%3}, {%4,%5,%6,%7}, {%8,%9}, {%0,%1,%2,%3};"
        : "+f"(c[0]), "+f"(c[1]), "+f"(c[2]), "+f"(c[3])
        : "r"(a[0]), "r"(a[1]), "r"(a[2]), "r"(a[3]), "r"(b[0]), "r"(b[1]));
}

__device__ __forceinline__ uint32_t tf32rn(float x) {
    uint32_t u; asm("cvt.rn.tf32.f32 %0, %1;" : "=r"(u) : "f"(x)); return u;
}

// exp2(z) on the FFMA pipe, z in [-150, 0]
__device__ __forceinline__ float fexp2_poly(float z) {
    const float MAGIC = 12582912.0f;         // 1.5*2^23
    float rr = z + MAGIC;
    float f  = z - (rr - MAGIC);             // frac in [-0.5,0.5]
    float p  = 0.0013333558f;
    p = fmaf(p, f, 0.0096181291f);
    p = fmaf(p, f, 0.0555041087f);
    p = fmaf(p, f, 0.2402265069f);
    p = fmaf(p, f, 0.6931471806f);
    p = fmaf(p, f, 1.0f);
    int ir = __float_as_int(rr);
    float s1 = __int_as_float((int)(((unsigned)ir + 199u) << 23));  // 2^(n+72)
    return p * s1 * 2.1175824e-22f;          // * 2^-72
}

// ---------------------------------------------------------------------------
// Prepass: RN-round K,V to tf32 (avoids in-MMA RZ truncation bias)
__global__ void roundkv_kernel(const float* __restrict__ K, const float* __restrict__ V) {
    size_t i = (size_t)blockIdx.x * 256 + threadIdx.x;   // one float4 of each
    const float4 k4 = ((const float4*)K)[i];
    const float4 v4 = ((const float4*)V)[i];
    uint4 ko, vo;
    ko.x = tf32rn(k4.x); ko.y = tf32rn(k4.y); ko.z = tf32rn(k4.z); ko.w = tf32rn(k4.w);
    vo.x = tf32rn(v4.x); vo.y = tf32rn(v4.y); vo.z = tf32rn(v4.z); vo.w = tf32rn(v4.w);
    ((uint4*)g_kr)[i] = ko;
    ((uint4*)g_vr)[i] = vo;
}

// ---------------------------------------------------------------------------
__global__ void __launch_bounds__(NTHR, 1)
attn_mma_kernel(const float* __restrict__ Q, float* __restrict__ Out)
{
    extern __shared__ float sm[];
    const int tid  = threadIdx.x;
    const int wid  = tid >> 5;
    const int lane = tid & 31;
    const int g    = lane >> 2;        // 0..7
    const int lm   = lane & 3;         // 0..3
    const int rw   = wid & 3;          // row-group
    const int cw   = wid >> 2;         // col-group
    const int rA   = rw * 32 + g;      // fragment row base
    const int cB   = cw * 32;          // score col base
    const int cV   = cw * 64;          // PV col base

    const int bidx = blockIdx.x;
    const int qt   = (NQT - 1) - (bidx >> 5);   // heavy CTAs first
    const int bh   = bidx & 31;
    const int l0   = qt * BM;
    const int tmax = 2 * qt + 1;                // kv tiles 0..tmax (BN=64)

    const float* Qg = Q + ((size_t)bh * LL + l0) * DD;
    const float* Kg = g_kr + (size_t)bh * LL * DD;
    const float* Vg = g_vr + (size_t)bh * LL * DD;

    // ---- Q tile: scale by 1/sqrt(D), RN-round to tf32, store to SMEM
    {
        const float sc = 0.08838834764831845f;
#pragma unroll
        for (int i = 0; i < 16; ++i) {
            int f = i * NTHR + tid;
            int row = f >> 5, c4 = (f & 31) * 4;
            float4 v = ((const float4*)Qg)[f];
            uint4 u;
            u.x = tf32rn(v.x * sc); u.y = tf32rn(v.y * sc);
            u.z = tf32rn(v.z * sc); u.w = tf32rn(v.w * sc);
            *(uint4*)&sm[QS_OFF + row * QS_STR + c4] = u;
        }
    }

    // ---- prefetch K(0), V(0)
    const uint32_t suK = smem_u32(&sm[KS_OFF]);
    const uint32_t suV = smem_u32(&sm[VS_OFF]);
    {
#pragma unroll
        for (int i = 0; i < 8; ++i) {
            int c = i * NTHR + tid;
            int row = c >> 5, c4 = (c & 31) * 4;
            CP_ASYNC16(suK + (row * KS_STR + c4) * 4, Kg + (size_t)row * DD + c4);
            CP_ASYNC16(suV + (row * VS_STR + c4) * 4, Vg + (size_t)row * DD + c4);
        }
        CP_COMMIT();
    }

    float O[2][8][4];
#pragma unroll
    for (int rt = 0; rt < 2; ++rt)
#pragma unroll
        for (int nt = 0; nt < 8; ++nt)
#pragma unroll
            for (int c = 0; c < 4; ++c) O[rt][nt][c] = 0.f;
    float rho[2][2] = {{0.f, 0.f}, {0.f, 0.f}};

    for (int t = 0; t <= tmax; ++t) {
        const int s0 = t * BN;
        const int vb = VS_OFF + (t & 1) * VS_BUF;

        CP_WAIT0();
        __syncthreads();   // K(t), V(t) resident; prior-tile PV done

        // ---- score GEMM: S = Qtile @ Ktile^T  (tf32)
        float S[2][4][4];
#pragma unroll
        for (int rt = 0; rt < 2; ++rt)
#pragma unroll
            for (int nt = 0; nt < 4; ++nt)
#pragma unroll
                for (int c = 0; c < 4; ++c) S[rt][nt][c] = 0.f;

#pragma unroll
        for (int kk = 0; kk < 16; ++kk) {
            const int kc = kk * 8 + lm;
            uint32_t a[2][4], b[4][2];
#pragma unroll
            for (int rt = 0; rt < 2; ++rt) {
                const float* qp = &sm[QS_OFF + (rA + rt * 16) * QS_STR + kc];
                a[rt][0] = __float_as_uint(qp[0]);
                a[rt][1] = __float_as_uint(qp[8 * QS_STR]);
                a[rt][2] = __float_as_uint(qp[4]);
                a[rt][3] = __float_as_uint(qp[8 * QS_STR + 4]);
            }
#pragma unroll
            for (int nt = 0; nt < 4; ++nt) {
                const float* kp = &sm[KS_OFF + (cB + nt * 8 + g) * KS_STR + kc];
                b[nt][0] = __float_as_uint(kp[0]);
                b[nt][1] = __float_as_uint(kp[4]);
            }
#pragma unroll
            for (int rt = 0; rt < 2; ++rt)
#pragma unroll
                for (int nt = 0; nt < 4; ++nt)
                    mma_tf32(S[rt][nt], a[rt], b[nt]);
        }
        __syncthreads();   // everyone done reading K buffer

        // ---- prefetch K(t+1), V(t+1) (overlaps softmax + PV)
        if (t < tmax) {
            const float* Kn = Kg + (size_t)(s0 + BN) * DD;
            const float* Vn = Vg + (size_t)(s0 + BN) * DD;
            const uint32_t suVn = suV + ((~t & 1) * VS_BUF) * 4;
#pragma unroll
            for (int i = 0; i < 8; ++i) {
                int c = i * NTHR + tid;
                int row = c >> 5, c4 = (c & 31) * 4;
                CP_ASYNC16(suK + (row * KS_STR + c4) * 4, Kn + (size_t)row * DD + c4);
                CP_ASYNC16(suVn + (row * VS_STR + c4) * 4, Vn + (size_t)row * DD + c4);
            }
        }
        CP_COMMIT();

        // ---- softmax (fixed max = 50): p = exp2(min(s*log2e - 50*log2e, 0))
        const bool diag = (t >= 2 * qt);
#pragma unroll
        for (int rt = 0; rt < 2; ++rt) {
            float rs0 = 0.f, rs1 = 0.f;
#pragma unroll
            for (int nt = 0; nt < 4; ++nt) {
                const int colg = s0 + cB + nt * 8 + 2 * lm;
                const int rowg = l0 + rA + rt * 16;
                float p[4];
#pragma unroll
                for (int c = 0; c < 4; ++c) {
                    float z = fminf(fmaf(S[rt][nt][c], 1.4426950408889634f,
                                         -72.13475204444817f), 0.f);
                    float e;
                    if (c & 1) { asm("ex2.approx.f32 %0, %1;" : "=f"(e) : "f"(z)); }
                    else       { e = fexp2_poly(z); }
                    if (diag && (colg + (c & 1)) > (rowg + (c >> 1) * 8)) e = 0.f;
                    p[c] = __uint_as_float(tf32rn(e));
                }
                rs0 += p[0] + p[1];
                rs1 += p[2] + p[3];
                // P -> SMEM (A-operand layout for PV)
                float* pp = &sm[PS_OFF + (rA + rt * 16) * PS_STR + cB + nt * 8 + 2 * lm];
                *(float2*)pp               = make_float2(p[0], p[1]);
                *(float2*)(pp + 8 * PS_STR) = make_float2(p[2], p[3]);
            }
            rs0 += __shfl_xor_sync(0xffffffffu, rs0, 1);
            rs0 += __shfl_xor_sync(0xffffffffu, rs0, 2);
            rs1 += __shfl_xor_sync(0xffffffffu, rs1, 1);
            rs1 += __shfl_xor_sync(0xffffffffu, rs1, 2);
            rho[rt][0] += rs0;
            rho[rt][1] += rs1;
        }
        __syncthreads();   // P visible to the other col-group warp

        // ---- PV GEMM: O += P @ Vtile  (tf32)
#pragma unroll
        for (int kk = 0; kk < 8; ++kk) {
            const int kc = kk * 8 + lm;
            uint32_t a[2][4], b[8][2];
#pragma unroll
            for (int rt = 0; rt < 2; ++rt) {
                const float* pp = &sm[PS_OFF + (rA + rt * 16) * PS_STR + kc];
                a[rt][0] = __float_as_uint(pp[0]);
                a[rt][1] = __float_as_uint(pp[8 * PS_STR]);
                a[rt][2] = __float_as_uint(pp[4]);
                a[rt][3] = __float_as_uint(pp[8 * PS_STR + 4]);
            }
#pragma unroll
            for (int nt = 0; nt < 8; ++nt) {
                const float* vp = &sm[vb + kc * VS_STR + cV + nt * 8 + g];
                b[nt][0] = __float_as_uint(vp[0]);
                b[nt][1] = __float_as_uint(vp[4 * VS_STR]);
            }
#pragma unroll
            for (int rt = 0; rt < 2; ++rt)
#pragma unroll
                for (int nt = 0; nt < 8; ++nt)
                    mma_tf32(O[rt][nt], a[rt], b[nt]);
        }
    }

    // ---- epilogue: combine rho across col-groups, normalize, store
    if (lm == 0) {
#pragma unroll
        for (int rt = 0; rt < 2; ++rt) {
            sm[RHO_OFF + cw * 128 + rA + rt * 16]     = rho[rt][0];
            sm[RHO_OFF + cw * 128 + rA + rt * 16 + 8] = rho[rt][1];
        }
    }
    __syncthreads();
#pragma unroll
    for (int rt = 0; rt < 2; ++rt) {
        const int row0 = rA + rt * 16;
        float inv0 = 1.f / (sm[RHO_OFF + row0]     + sm[RHO_OFF + 128 + row0]);
        float inv1 = 1.f / (sm[RHO_OFF + row0 + 8] + sm[RHO_OFF + 128 + row0 + 8]);
        float* o0 = Out + ((size_t)bh * LL + l0 + row0) * DD + cV + 2 * lm;
        float* o1 = o0 + 8 * DD;
#pragma unroll
        for (int nt = 0; nt < 8; ++nt) {
            *(float2*)(o0 + nt * 8) = make_float2(O[rt][nt][0] * inv0, O[rt][nt][1] * inv0);
            *(float2*)(o1 + nt * 8) = make_float2(O[rt][nt][2] * inv1, O[rt][nt][3] * inv1);
        }
    }
}

// ---------------------------------------------------------------------------
extern "C" void kernel_launch(void* const* d_in, const int* in_sizes, int n_in,
                              void* d_out, int out_size) {
    (void)in_sizes; (void)n_in; (void)out_size;
    const float* q = (const float*)d_in[0];
    const float* k = (const float*)d_in[1];
    const float* v = (const float*)d_in[2];

    // total float4 elems per tensor: BH*LL*DD/4 = 2,097,152 -> 8192 blocks x 256
    roundkv_kernel<<<8192, 256>>>(k, v);

    cudaFuncSetAttribute(attn_mma_kernel,
                         cudaFuncAttributeMaxDynamicSharedMemorySize, SMEM_BYTES);
    attn_mma_kernel<<<NQT * BH, NTHR, SMEM_BYTES>>>(q, (float*)d_out);
}